// round 1
// baseline (speedup 1.0000x reference)
#include <cuda_runtime.h>
#include <cuda_bf16.h>
#include <math.h>

// Problem constants
#define BB 2
#define NN 2048
#define CC 1024
#define HH 16
#define DH 64
#define MLPD 4096
#define MM (BB*NN)          // 4096 tokens
#define C3 (3*CC)           // 3072

// ---------------- scratch (static device globals; no allocation) ----------------
__device__ float g_x1[MM*CC];      // x + pos (residual stream 1)
__device__ float g_h[MM*CC];       // LN1 out
__device__ float g_qkv[MM*C3];     // qkv (+lora)
__device__ float g_afterA[MM*8];   // h @ lora_A^T
__device__ float g_attn[MM*CC];    // attention output (B,N,C)
__device__ float g_x2[MM*CC];      // after attn residual
__device__ float g_h2[MM*CC];      // LN2 out
__device__ float g_mlp[MM*MLPD];   // gelu(h2 W1^T + b1)

// ---------------- fused (x+pos) + LayerNorm ----------------
// one block per row of C=1024, 256 threads, 4 elems/thread, two-pass LN.
__global__ void addpos_ln_kernel(const float* __restrict__ x,
                                 const float* __restrict__ pos,
                                 const float* __restrict__ g,
                                 const float* __restrict__ b,
                                 float* __restrict__ x1out,
                                 float* __restrict__ hout) {
    int row = blockIdx.x;
    int t = threadIdx.x;
    const float* xr = x + row * CC;
    float v[4];
#pragma unroll
    for (int i = 0; i < 4; i++) {
        int c = t + i * 256;
        float val = xr[c];
        if (pos) val += pos[row * CC + c];
        v[i] = val;
        if (x1out) x1out[row * CC + c] = val;
    }
    __shared__ float sred[256];
    float s = v[0] + v[1] + v[2] + v[3];
    sred[t] = s; __syncthreads();
    for (int o = 128; o > 0; o >>= 1) { if (t < o) sred[t] += sred[t + o]; __syncthreads(); }
    float mean = sred[0] * (1.0f / CC);
    __syncthreads();
    float sq = 0.f;
#pragma unroll
    for (int i = 0; i < 4; i++) { float d = v[i] - mean; sq += d * d; }
    sred[t] = sq; __syncthreads();
    for (int o = 128; o > 0; o >>= 1) { if (t < o) sred[t] += sred[t + o]; __syncthreads(); }
    float rstd = rsqrtf(sred[0] * (1.0f / CC) + 1e-5f);
#pragma unroll
    for (int i = 0; i < 4; i++) {
        int c = t + i * 256;
        hout[row * CC + c] = (v[i] - mean) * rstd * g[c] + b[c];
    }
}

// ---------------- tiled fp32 GEMM:  C[M,N] = A[M,K] * B[N,K]^T + bias (+gelu)(+res) ----------------
// 128x128 tile, BK=8, 256 threads, 8x8 per thread with fragments split at +-64.
// Requires M%128==0, N%128==0, K%8==0 (true for all calls here).
__global__ void __launch_bounds__(256)
gemm_nt_kernel(const float* __restrict__ A, const float* __restrict__ B,
               const float* __restrict__ bias, const float* __restrict__ res,
               float* __restrict__ Cout, int M, int Ncols, int K, int act) {
    __shared__ float As[8][128];
    __shared__ float Bs[8][128];
    int tid = threadIdx.x;
    int tx = tid & 15;        // 0..15 -> col fragments tx*4 and 64+tx*4
    int ty = tid >> 4;        // 0..15 -> row fragments ty*4 and 64+ty*4
    int bm = blockIdx.y * 128;
    int bn = blockIdx.x * 128;

    int lrow = tid >> 1;            // 0..127
    int lcol = (tid & 1) * 4;       // 0 or 4
    const float* Aptr = A + (size_t)(bm + lrow) * K + lcol;
    const float* Bptr = B + (size_t)(bn + lrow) * K + lcol;

    float acc[8][8];
#pragma unroll
    for (int i = 0; i < 8; i++)
#pragma unroll
        for (int j = 0; j < 8; j++) acc[i][j] = 0.f;

    for (int k0 = 0; k0 < K; k0 += 8) {
        float4 av = *(const float4*)(Aptr + k0);
        float4 bv = *(const float4*)(Bptr + k0);
        As[lcol + 0][lrow] = av.x; As[lcol + 1][lrow] = av.y;
        As[lcol + 2][lrow] = av.z; As[lcol + 3][lrow] = av.w;
        Bs[lcol + 0][lrow] = bv.x; Bs[lcol + 1][lrow] = bv.y;
        Bs[lcol + 2][lrow] = bv.z; Bs[lcol + 3][lrow] = bv.w;
        __syncthreads();
#pragma unroll
        for (int k = 0; k < 8; k++) {
            float4 a0 = *(const float4*)&As[k][ty * 4];
            float4 a1 = *(const float4*)&As[k][64 + ty * 4];
            float4 b0 = *(const float4*)&Bs[k][tx * 4];
            float4 b1 = *(const float4*)&Bs[k][64 + tx * 4];
            float af[8] = {a0.x, a0.y, a0.z, a0.w, a1.x, a1.y, a1.z, a1.w};
            float bf[8] = {b0.x, b0.y, b0.z, b0.w, b1.x, b1.y, b1.z, b1.w};
#pragma unroll
            for (int i = 0; i < 8; i++)
#pragma unroll
                for (int j = 0; j < 8; j++)
                    acc[i][j] = fmaf(af[i], bf[j], acc[i][j]);
        }
        __syncthreads();
    }

    // epilogue: bias, optional gelu, optional residual, vectorized float4 stores
#pragma unroll
    for (int i = 0; i < 8; i++) {
        int r = bm + ((i < 4) ? (ty * 4 + i) : (64 + ty * 4 + i - 4));
#pragma unroll
        for (int half = 0; half < 2; half++) {
            int c0 = bn + half * 64 + tx * 4;
            float4 bi = *(const float4*)&bias[c0];
            float vv[4];
#pragma unroll
            for (int j = 0; j < 4; j++) {
                float v = acc[i][half * 4 + j] + ((const float*)&bi)[j];
                if (act == 1) {
                    v = 0.5f * v * (1.0f + erff(v * 0.70710678118654752f));
                }
                vv[j] = v;
            }
            if (res) {
                float4 rv = *(const float4*)&res[(size_t)r * Ncols + c0];
                vv[0] += rv.x; vv[1] += rv.y; vv[2] += rv.z; vv[3] += rv.w;
            }
            float4 outv = make_float4(vv[0], vv[1], vv[2], vv[3]);
            *(float4*)&Cout[(size_t)r * Ncols + c0] = outv;
        }
    }
}

// ---------------- LoRA: afterA = h @ lora_A^T  [M,8] ----------------
__global__ void lora_afterA_kernel(const float* __restrict__ h,
                                   const float* __restrict__ Amat,
                                   float* __restrict__ outA) {
    int m = blockIdx.x;
    int t = threadIdx.x;
    float acc[8] = {0, 0, 0, 0, 0, 0, 0, 0};
    const float* hr = h + m * CC;
    for (int c = t; c < CC; c += 256) {
        float hv = hr[c];
#pragma unroll
        for (int r = 0; r < 8; r++) acc[r] = fmaf(hv, Amat[r * CC + c], acc[r]);
    }
#pragma unroll
    for (int r = 0; r < 8; r++)
#pragma unroll
        for (int o = 16; o > 0; o >>= 1)
            acc[r] += __shfl_down_sync(0xffffffffu, acc[r], o);
    __shared__ float sw[8][8];
    int warp = t >> 5, lane = t & 31;
    if (lane == 0) {
#pragma unroll
        for (int r = 0; r < 8; r++) sw[warp][r] = acc[r];
    }
    __syncthreads();
    if (t < 8) {
        float s = 0.f;
#pragma unroll
        for (int w = 0; w < 8; w++) s += sw[w][t];
        outA[m * 8 + t] = s;
    }
}

// ---------------- LoRA apply: qkv[:, :C] += dq ; qkv[:, 2C:] += dv ----------------
__global__ void lora_apply_kernel(const float* __restrict__ afterA,
                                  const float* __restrict__ Bm,   // [2C, 4]
                                  float* __restrict__ qkv) {
    int idx = blockIdx.x * blockDim.x + threadIdx.x;   // < MM*CC
    int m = idx >> 10;
    int c = idx & 1023;
    const float* a = afterA + m * 8;
    float dq = 0.f, dv = 0.f;
#pragma unroll
    for (int r = 0; r < 4; r++) {
        dq = fmaf(a[r],     Bm[c * 4 + r],          dq);
        dv = fmaf(a[4 + r], Bm[(CC + c) * 4 + r],   dv);
    }
    qkv[(size_t)m * C3 + c]            += 0.25f * dq;
    qkv[(size_t)m * C3 + 2 * CC + c]   += 0.25f * dv;
}

// ---------------- flash attention (fp32, online softmax) ----------------
// grid (N/128, H, B), 128 threads; each thread owns one query row (q[64], acc[64] in regs).
__global__ void __launch_bounds__(128)
attn_kernel(const float* __restrict__ qkv, float* __restrict__ out) {
    int b = blockIdx.z, h = blockIdx.y;
    int qi = blockIdx.x * 128 + threadIdx.x;
    const float scale = 0.125f;   // 1/sqrt(64)

    float q[DH], acc[DH];
    const float* qrow = qkv + ((size_t)(b * NN + qi)) * C3 + h * DH;
#pragma unroll
    for (int d = 0; d < DH; d++) { q[d] = qrow[d] * scale; acc[d] = 0.f; }

    float mmax = -1e30f, l = 0.f;
    __shared__ float Ks[64][DH];
    __shared__ float Vs[64][DH];

    for (int kt = 0; kt < NN; kt += 64) {
        // cooperative load of 64 K rows + 64 V rows (float4, coalesced along d)
        for (int i = threadIdx.x; i < 64 * 16; i += 128) {
            int r = i >> 4;
            int d4 = (i & 15) * 4;
            const float* kp = qkv + ((size_t)(b * NN + kt + r)) * C3 + CC + h * DH + d4;
            float4 kv = *(const float4*)kp;
            float4 vv = *(const float4*)(kp + CC);   // v is +C after k
            *(float4*)&Ks[r][d4] = kv;
            *(float4*)&Vs[r][d4] = vv;
        }
        __syncthreads();
#pragma unroll 4
        for (int j = 0; j < 64; j++) {
            float s = 0.f;
#pragma unroll
            for (int d = 0; d < DH; d++) s = fmaf(q[d], Ks[j][d], s);
            float mnew = fmaxf(mmax, s);
            float corr = __expf(mmax - mnew);
            float p = __expf(s - mnew);
            l = fmaf(l, corr, p);
            mmax = mnew;
#pragma unroll
            for (int d = 0; d < DH; d++)
                acc[d] = fmaf(p, Vs[j][d], acc[d] * corr);
        }
        __syncthreads();
    }
    float inv = 1.f / l;
    float* orow = out + ((size_t)(b * NN + qi)) * CC + h * DH;
#pragma unroll
    for (int d = 0; d < DH; d++) orow[d] = acc[d] * inv;
}

// ---------------- launch ----------------
extern "C" void kernel_launch(void* const* d_in, const int* in_sizes, int n_in,
                              void* d_out, int out_size) {
    const float* x      = (const float*)d_in[0];
    const float* pos    = (const float*)d_in[1];
    const float* Wqkv   = (const float*)d_in[2];
    const float* b_qkv  = (const float*)d_in[3];
    const float* lora_A = (const float*)d_in[4];
    const float* lora_B = (const float*)d_in[5];
    const float* Wproj  = (const float*)d_in[6];
    const float* b_proj = (const float*)d_in[7];
    const float* ln1_g  = (const float*)d_in[8];
    const float* ln1_b  = (const float*)d_in[9];
    const float* ln2_g  = (const float*)d_in[10];
    const float* ln2_b  = (const float*)d_in[11];
    const float* W1     = (const float*)d_in[12];
    const float* b1     = (const float*)d_in[13];
    const float* W2     = (const float*)d_in[14];
    const float* b2     = (const float*)d_in[15];
    float* out = (float*)d_out;

    float *p_x1, *p_h, *p_qkv, *p_afterA, *p_attn, *p_x2, *p_h2, *p_mlp;
    cudaGetSymbolAddress((void**)&p_x1, g_x1);
    cudaGetSymbolAddress((void**)&p_h, g_h);
    cudaGetSymbolAddress((void**)&p_qkv, g_qkv);
    cudaGetSymbolAddress((void**)&p_afterA, g_afterA);
    cudaGetSymbolAddress((void**)&p_attn, g_attn);
    cudaGetSymbolAddress((void**)&p_x2, g_x2);
    cudaGetSymbolAddress((void**)&p_h2, g_h2);
    cudaGetSymbolAddress((void**)&p_mlp, g_mlp);

    // 1) x1 = x + pos ; h = LN1(x1)
    addpos_ln_kernel<<<MM, 256>>>(x, pos, ln1_g, ln1_b, p_x1, p_h);

    // 2) qkv = h @ Wqkv^T + b_qkv
    gemm_nt_kernel<<<dim3(C3 / 128, MM / 128), 256>>>(
        p_h, Wqkv, b_qkv, nullptr, p_qkv, MM, C3, CC, 0);

    // 3) LoRA
    lora_afterA_kernel<<<MM, 256>>>(p_h, lora_A, p_afterA);
    lora_apply_kernel<<<(MM * CC) / 256, 256>>>(p_afterA, lora_B, p_qkv);

    // 4) attention
    attn_kernel<<<dim3(NN / 128, HH, BB), 128>>>(p_qkv, p_attn);

    // 5) x2 = x1 + attn @ Wproj^T + b_proj
    gemm_nt_kernel<<<dim3(CC / 128, MM / 128), 256>>>(
        p_attn, Wproj, b_proj, p_x1, p_x2, MM, CC, CC, 0);

    // 6) h2 = LN2(x2)
    addpos_ln_kernel<<<MM, 256>>>(p_x2, nullptr, ln2_g, ln2_b, nullptr, p_h2);

    // 7) mlp = gelu(h2 @ W1^T + b1)
    gemm_nt_kernel<<<dim3(MLPD / 128, MM / 128), 256>>>(
        p_h2, W1, b1, nullptr, p_mlp, MM, MLPD, CC, 1);

    // 8) out = x2 + mlp @ W2^T + b2
    gemm_nt_kernel<<<dim3(CC / 128, MM / 128), 256>>>(
        p_mlp, W2, b2, p_x2, out, MM, CC, MLPD, 0);
}

// round 2
// speedup vs baseline: 1.8941x; 1.8941x over previous
#include <cuda_runtime.h>
#include <cuda_bf16.h>
#include <math.h>
#include <stdint.h>

// Problem constants
#define BB 2
#define NN 2048
#define CC 1024
#define HH 16
#define DH 64
#define MLPD 4096
#define MM (BB*NN)          // 4096 tokens
#define C3 (3*CC)           // 3072

// ---------------- scratch (static device globals; no allocation) ----------------
__device__ float g_x1[MM*CC];      // x + pos (residual stream 1)
__device__ float g_h[MM*CC];       // LN1 out (tf32-rounded)
__device__ float g_qkv[MM*C3];     // qkv (+lora)
__device__ float g_afterA[MM*8];   // h @ lora_A^T
__device__ float g_attn[MM*CC];    // attention output (tf32-rounded)
__device__ float g_x2[MM*CC];      // after attn residual
__device__ float g_h2[MM*CC];      // LN2 out (tf32-rounded)
__device__ float g_mlp[MM*MLPD];   // gelu(...) (tf32-rounded)
__device__ float g_wqkv_r[C3*CC];
__device__ float g_wproj_r[CC*CC];
__device__ float g_w1_r[MLPD*CC];
__device__ float g_w2_r[CC*MLPD];

__device__ __forceinline__ float rna_tf32(float x) {
    uint32_t u;
    asm("cvt.rna.tf32.f32 %0, %1;" : "=r"(u) : "f"(x));
    return __uint_as_float(u);
}

#define CP_ASYNC16(dst, src) \
    asm volatile("cp.async.ca.shared.global [%0], [%1], 16;" :: "r"(dst), "l"(src))
#define CP_COMMIT() asm volatile("cp.async.commit_group;")
#define CP_WAIT(n)  asm volatile("cp.async.wait_group %0;" :: "n"(n))

#define LDMATRIX_X4(r0, r1, r2, r3, addr) \
    asm volatile("ldmatrix.sync.aligned.m8n8.x4.shared.b16 {%0,%1,%2,%3}, [%4];" \
                 : "=r"(r0), "=r"(r1), "=r"(r2), "=r"(r3) : "r"(addr))

#define MMA_TF32(c0, c1, c2, c3, a0, a1, a2, a3, b0, b1) \
    asm volatile("mma.sync.aligned.m16n8k8.row.col.f32.tf32.tf32.f32 " \
                 "{%0,%1,%2,%3}, {%4,%5,%6,%7}, {%8,%9}, {%0,%1,%2,%3};" \
                 : "+f"(c0), "+f"(c1), "+f"(c2), "+f"(c3) \
                 : "r"(a0), "r"(a1), "r"(a2), "r"(a3), "r"(b0), "r"(b1))

// ---------------- weight rounding: out[i] = rna_tf32(in[i]) ----------------
__global__ void round_tf32_kernel(const float* __restrict__ in,
                                  float* __restrict__ out, int n4) {
    int i = blockIdx.x * blockDim.x + threadIdx.x;
    if (i < n4) {
        float4 v = ((const float4*)in)[i];
        v.x = rna_tf32(v.x); v.y = rna_tf32(v.y);
        v.z = rna_tf32(v.z); v.w = rna_tf32(v.w);
        ((float4*)out)[i] = v;
    }
}

// ---------------- fused (x+pos) + LayerNorm (output tf32-rounded) ----------------
__global__ void addpos_ln_kernel(const float* __restrict__ x,
                                 const float* __restrict__ pos,
                                 const float* __restrict__ g,
                                 const float* __restrict__ b,
                                 float* __restrict__ x1out,
                                 float* __restrict__ hout) {
    int row = blockIdx.x;
    int t = threadIdx.x;
    const float* xr = x + row * CC;
    float v[4];
#pragma unroll
    for (int i = 0; i < 4; i++) {
        int c = t + i * 256;
        float val = xr[c];
        if (pos) val += pos[row * CC + c];
        v[i] = val;
        if (x1out) x1out[row * CC + c] = val;
    }
    __shared__ float sred[256];
    float s = v[0] + v[1] + v[2] + v[3];
    sred[t] = s; __syncthreads();
    for (int o = 128; o > 0; o >>= 1) { if (t < o) sred[t] += sred[t + o]; __syncthreads(); }
    float mean = sred[0] * (1.0f / CC);
    __syncthreads();
    float sq = 0.f;
#pragma unroll
    for (int i = 0; i < 4; i++) { float d = v[i] - mean; sq += d * d; }
    sred[t] = sq; __syncthreads();
    for (int o = 128; o > 0; o >>= 1) { if (t < o) sred[t] += sred[t + o]; __syncthreads(); }
    float rstd = rsqrtf(sred[0] * (1.0f / CC) + 1e-5f);
#pragma unroll
    for (int i = 0; i < 4; i++) {
        int c = t + i * 256;
        hout[row * CC + c] = rna_tf32((v[i] - mean) * rstd * g[c] + b[c]);
    }
}

// ---------------- TF32 tensor-core GEMM: C = A[M,K] * B[N,K]^T + bias (+gelu)(+res)(+round) ----------------
// 128x128x32 tiles, 256 threads = 8 warps (2m x 4n), warp tile 64x32.
// cp.async double-buffered, 128B-swizzled smem, ldmatrix fragments.
__global__ void __launch_bounds__(256)
gemm_tf32_kernel(const float* __restrict__ A, const float* __restrict__ B,
                 const float* __restrict__ bias, const float* __restrict__ res,
                 float* __restrict__ Cout, int M, int Ncols, int K,
                 int act, int rnd) {
    extern __shared__ float smf[];
    uint32_t smbase = (uint32_t)__cvta_generic_to_shared(smf);
    // layout: stage0 A [0,16384), stage1 A [16384,32768), stage0 B [32768,49152), stage1 B [49152,65536)
    const int tid = threadIdx.x;
    const int lane = tid & 31;
    const int warp = tid >> 5;
    const int warp_m = warp & 1;       // 0/1  -> m offset 64*warp_m
    const int warp_n = warp >> 1;      // 0..3 -> n offset 32*warp_n
    const int bm = blockIdx.y * 128;
    const int bn = blockIdx.x * 128;

    // ldmatrix per-lane invariants
    const int a_lrow = lane & 15;           // row within 16-row tile
    const int a_lch  = lane >> 4;           // 0/1 -> +16B k-chunk
    const int b_nrow = (lane & 7) + ((lane >> 4) << 3);
    const int b_kc   = (lane & 8) >> 3;

    float acc[4][4][4];
#pragma unroll
    for (int i = 0; i < 4; i++)
#pragma unroll
        for (int j = 0; j < 4; j++)
#pragma unroll
            for (int r = 0; r < 4; r++) acc[i][j][r] = 0.f;

    const int Ksteps = K >> 5;   // K/32

    // ---- tile copy (global -> smem stage s, k offset kk) ----
    auto load_tile = [&](int s, int kk) {
        uint32_t a_base = smbase + s * 16384;
        uint32_t b_base = smbase + 32768 + s * 16384;
#pragma unroll
        for (int i = 0; i < 4; i++) {
            int id = tid + i * 256;           // 0..1023
            int row = id >> 3, ch = id & 7;
            const float* srcA = A + (size_t)(bm + row) * K + kk + ch * 4;
            uint32_t dstA = a_base + row * 128 + (((ch ^ (row & 7))) << 4);
            CP_ASYNC16(dstA, srcA);
        }
#pragma unroll
        for (int i = 0; i < 4; i++) {
            int id = tid + i * 256;
            int row = id >> 3, ch = id & 7;
            const float* srcB = B + (size_t)(bn + row) * K + kk + ch * 4;
            uint32_t dstB = b_base + row * 128 + (((ch ^ (row & 7))) << 4);
            CP_ASYNC16(dstB, srcB);
        }
    };

    load_tile(0, 0);
    CP_COMMIT();

    for (int s = 0; s < Ksteps; s++) {
        int buf = s & 1;
        if (s + 1 < Ksteps) {
            load_tile(buf ^ 1, (s + 1) << 5);
            CP_COMMIT();
            CP_WAIT(1);
        } else {
            CP_WAIT(0);
        }
        __syncthreads();

        uint32_t a_base = smbase + buf * 16384;
        uint32_t b_base = smbase + 32768 + buf * 16384;

#pragma unroll
        for (int ks = 0; ks < 4; ks++) {
            uint32_t af[4][4];
#pragma unroll
            for (int mt = 0; mt < 4; mt++) {
                int m = warp_m * 64 + mt * 16 + a_lrow;
                int chunk = ks * 2 + a_lch;
                uint32_t addr = a_base + m * 128 + ((chunk ^ (m & 7)) << 4);
                LDMATRIX_X4(af[mt][0], af[mt][1], af[mt][2], af[mt][3], addr);
            }
            uint32_t bf[2][4];
#pragma unroll
            for (int p = 0; p < 2; p++) {
                int n = warp_n * 32 + p * 16 + b_nrow;
                int chunk = ks * 2 + b_kc;
                uint32_t addr = b_base + n * 128 + ((chunk ^ (n & 7)) << 4);
                LDMATRIX_X4(bf[p][0], bf[p][1], bf[p][2], bf[p][3], addr);
            }
#pragma unroll
            for (int mt = 0; mt < 4; mt++)
#pragma unroll
                for (int nt = 0; nt < 4; nt++) {
                    uint32_t b0 = bf[nt >> 1][(nt & 1) * 2];
                    uint32_t b1 = bf[nt >> 1][(nt & 1) * 2 + 1];
                    MMA_TF32(acc[mt][nt][0], acc[mt][nt][1], acc[mt][nt][2], acc[mt][nt][3],
                             af[mt][0], af[mt][1], af[mt][2], af[mt][3], b0, b1);
                }
        }
        __syncthreads();
    }

    // ---- epilogue ----
    const int gid = lane >> 2;       // 0..7
    const int tig = lane & 3;        // 0..3
#pragma unroll
    for (int mt = 0; mt < 4; mt++) {
#pragma unroll
        for (int nt = 0; nt < 4; nt++) {
            int col = bn + warp_n * 32 + nt * 8 + tig * 2;
            float bi0 = bias[col], bi1 = bias[col + 1];
#pragma unroll
            for (int half = 0; half < 2; half++) {
                int row = bm + warp_m * 64 + mt * 16 + gid + half * 8;
                float v0 = acc[mt][nt][half * 2 + 0] + bi0;
                float v1 = acc[mt][nt][half * 2 + 1] + bi1;
                if (act == 1) {
                    v0 = 0.5f * v0 * (1.0f + erff(v0 * 0.70710678118654752f));
                    v1 = 0.5f * v1 * (1.0f + erff(v1 * 0.70710678118654752f));
                }
                if (res) {
                    v0 += res[(size_t)row * Ncols + col];
                    v1 += res[(size_t)row * Ncols + col + 1];
                }
                if (rnd) { v0 = rna_tf32(v0); v1 = rna_tf32(v1); }
                float2 ov = make_float2(v0, v1);
                *(float2*)&Cout[(size_t)row * Ncols + col] = ov;
            }
        }
    }
}

// ---------------- LoRA: afterA = h @ lora_A^T  [M,8] ----------------
__global__ void lora_afterA_kernel(const float* __restrict__ h,
                                   const float* __restrict__ Amat,
                                   float* __restrict__ outA) {
    int m = blockIdx.x;
    int t = threadIdx.x;
    float acc[8] = {0, 0, 0, 0, 0, 0, 0, 0};
    const float* hr = h + m * CC;
    for (int c = t; c < CC; c += 256) {
        float hv = hr[c];
#pragma unroll
        for (int r = 0; r < 8; r++) acc[r] = fmaf(hv, Amat[r * CC + c], acc[r]);
    }
#pragma unroll
    for (int r = 0; r < 8; r++)
#pragma unroll
        for (int o = 16; o > 0; o >>= 1)
            acc[r] += __shfl_down_sync(0xffffffffu, acc[r], o);
    __shared__ float sw[8][8];
    int warp = t >> 5, lane = t & 31;
    if (lane == 0) {
#pragma unroll
        for (int r = 0; r < 8; r++) sw[warp][r] = acc[r];
    }
    __syncthreads();
    if (t < 8) {
        float s = 0.f;
#pragma unroll
        for (int w = 0; w < 8; w++) s += sw[w][t];
        outA[m * 8 + t] = s;
    }
}

// ---------------- LoRA apply ----------------
__global__ void lora_apply_kernel(const float* __restrict__ afterA,
                                  const float* __restrict__ Bm,   // [2C, 4]
                                  float* __restrict__ qkv) {
    int idx = blockIdx.x * blockDim.x + threadIdx.x;   // < MM*CC
    int m = idx >> 10;
    int c = idx & 1023;
    const float* a = afterA + m * 8;
    float dq = 0.f, dv = 0.f;
#pragma unroll
    for (int r = 0; r < 4; r++) {
        dq = fmaf(a[r],     Bm[c * 4 + r],        dq);
        dv = fmaf(a[4 + r], Bm[(CC + c) * 4 + r], dv);
    }
    qkv[(size_t)m * C3 + c]          += 0.25f * dq;
    qkv[(size_t)m * C3 + 2 * CC + c] += 0.25f * dv;
}

// ---------------- flash attention (fp32, online softmax; tf32-rounded output) ----------------
__global__ void __launch_bounds__(128)
attn_kernel(const float* __restrict__ qkv, float* __restrict__ out) {
    int b = blockIdx.z, h = blockIdx.y;
    int qi = blockIdx.x * 128 + threadIdx.x;
    const float scale = 0.125f;   // 1/sqrt(64)

    float q[DH], acc[DH];
    const float* qrow = qkv + ((size_t)(b * NN + qi)) * C3 + h * DH;
#pragma unroll
    for (int d = 0; d < DH; d++) { q[d] = qrow[d] * scale; acc[d] = 0.f; }

    float mmax = -1e30f, l = 0.f;
    __shared__ float Ks[64][DH];
    __shared__ float Vs[64][DH];

    for (int kt = 0; kt < NN; kt += 64) {
        for (int i = threadIdx.x; i < 64 * 16; i += 128) {
            int r = i >> 4;
            int d4 = (i & 15) * 4;
            const float* kp = qkv + ((size_t)(b * NN + kt + r)) * C3 + CC + h * DH + d4;
            float4 kv = *(const float4*)kp;
            float4 vv = *(const float4*)(kp + CC);
            *(float4*)&Ks[r][d4] = kv;
            *(float4*)&Vs[r][d4] = vv;
        }
        __syncthreads();
#pragma unroll 4
        for (int j = 0; j < 64; j++) {
            float s = 0.f;
#pragma unroll
            for (int d = 0; d < DH; d++) s = fmaf(q[d], Ks[j][d], s);
            float mnew = fmaxf(mmax, s);
            float corr = __expf(mmax - mnew);
            float p = __expf(s - mnew);
            l = fmaf(l, corr, p);
            mmax = mnew;
#pragma unroll
            for (int d = 0; d < DH; d++)
                acc[d] = fmaf(p, Vs[j][d], acc[d] * corr);
        }
        __syncthreads();
    }
    float inv = 1.f / l;
    float* orow = out + ((size_t)(b * NN + qi)) * CC + h * DH;
#pragma unroll
    for (int d = 0; d < DH; d++) orow[d] = rna_tf32(acc[d] * inv);
}

// ---------------- launch ----------------
extern "C" void kernel_launch(void* const* d_in, const int* in_sizes, int n_in,
                              void* d_out, int out_size) {
    const float* x      = (const float*)d_in[0];
    const float* pos    = (const float*)d_in[1];
    const float* Wqkv   = (const float*)d_in[2];
    const float* b_qkv  = (const float*)d_in[3];
    const float* lora_A = (const float*)d_in[4];
    const float* lora_B = (const float*)d_in[5];
    const float* Wproj  = (const float*)d_in[6];
    const float* b_proj = (const float*)d_in[7];
    const float* ln1_g  = (const float*)d_in[8];
    const float* ln1_b  = (const float*)d_in[9];
    const float* ln2_g  = (const float*)d_in[10];
    const float* ln2_b  = (const float*)d_in[11];
    const float* W1     = (const float*)d_in[12];
    const float* b1     = (const float*)d_in[13];
    const float* W2     = (const float*)d_in[14];
    const float* b2     = (const float*)d_in[15];
    float* out = (float*)d_out;

    float *p_x1, *p_h, *p_qkv, *p_afterA, *p_attn, *p_x2, *p_h2, *p_mlp;
    float *p_wqkv, *p_wproj, *p_w1, *p_w2;
    cudaGetSymbolAddress((void**)&p_x1, g_x1);
    cudaGetSymbolAddress((void**)&p_h, g_h);
    cudaGetSymbolAddress((void**)&p_qkv, g_qkv);
    cudaGetSymbolAddress((void**)&p_afterA, g_afterA);
    cudaGetSymbolAddress((void**)&p_attn, g_attn);
    cudaGetSymbolAddress((void**)&p_x2, g_x2);
    cudaGetSymbolAddress((void**)&p_h2, g_h2);
    cudaGetSymbolAddress((void**)&p_mlp, g_mlp);
    cudaGetSymbolAddress((void**)&p_wqkv, g_wqkv_r);
    cudaGetSymbolAddress((void**)&p_wproj, g_wproj_r);
    cudaGetSymbolAddress((void**)&p_w1, g_w1_r);
    cudaGetSymbolAddress((void**)&p_w2, g_w2_r);

    static bool attr_set = false;
    if (!attr_set) {
        cudaFuncSetAttribute(gemm_tf32_kernel,
                             cudaFuncAttributeMaxDynamicSharedMemorySize, 65536);
        attr_set = true;
    }

    // 0) round weights to tf32
    round_tf32_kernel<<<(C3 * CC / 4 + 255) / 256, 256>>>(Wqkv, p_wqkv, C3 * CC / 4);
    round_tf32_kernel<<<(CC * CC / 4 + 255) / 256, 256>>>(Wproj, p_wproj, CC * CC / 4);
    round_tf32_kernel<<<(MLPD * CC / 4 + 255) / 256, 256>>>(W1, p_w1, MLPD * CC / 4);
    round_tf32_kernel<<<(CC * MLPD / 4 + 255) / 256, 256>>>(W2, p_w2, CC * MLPD / 4);

    // 1) x1 = x + pos ; h = LN1(x1) (rounded)
    addpos_ln_kernel<<<MM, 256>>>(x, pos, ln1_g, ln1_b, p_x1, p_h);

    // 2) qkv = h @ Wqkv^T + b_qkv
    gemm_tf32_kernel<<<dim3(C3 / 128, MM / 128), 256, 65536>>>(
        p_h, p_wqkv, b_qkv, nullptr, p_qkv, MM, C3, CC, 0, 0);

    // 3) LoRA
    lora_afterA_kernel<<<MM, 256>>>(p_h, lora_A, p_afterA);
    lora_apply_kernel<<<(MM * CC) / 256, 256>>>(p_afterA, lora_B, p_qkv);

    // 4) attention (output rounded)
    attn_kernel<<<dim3(NN / 128, HH, BB), 128>>>(p_qkv, p_attn);

    // 5) x2 = x1 + attn @ Wproj^T + b_proj
    gemm_tf32_kernel<<<dim3(CC / 128, MM / 128), 256, 65536>>>(
        p_attn, p_wproj, b_proj, p_x1, p_x2, MM, CC, CC, 0, 0);

    // 6) h2 = LN2(x2) (rounded)
    addpos_ln_kernel<<<MM, 256>>>(p_x2, nullptr, ln2_g, ln2_b, nullptr, p_h2);

    // 7) mlp = gelu(h2 @ W1^T + b1) (rounded)
    gemm_tf32_kernel<<<dim3(MLPD / 128, MM / 128), 256, 65536>>>(
        p_h2, p_w1, b1, nullptr, p_mlp, MM, MLPD, CC, 1, 1);

    // 8) out = x2 + mlp @ W2^T + b2
    gemm_tf32_kernel<<<dim3(CC / 128, MM / 128), 256, 65536>>>(
        p_mlp, p_w2, b2, p_x2, out, MM, CC, MLPD, 0, 0);
}

// round 3
// speedup vs baseline: 3.3216x; 1.7537x over previous
#include <cuda_runtime.h>
#include <cuda_bf16.h>
#include <math.h>
#include <stdint.h>

// Problem constants
#define BB 2
#define NN 2048
#define CC 1024
#define HH 16
#define DH 64
#define MLPD 4096
#define MM (BB*NN)          // 4096 tokens
#define C3 (3*CC)           // 3072

// ---------------- scratch (static device globals; no allocation) ----------------
__device__ float g_x1[MM*CC];      // x + pos (residual stream 1)
__device__ float g_h[MM*CC];       // LN1 out (tf32-rounded)
__device__ float g_qkv[MM*C3];     // qkv (+lora)
__device__ float g_afterA[MM*8];   // h @ lora_A^T
__device__ float g_attn[MM*CC];    // attention output (tf32-rounded)
__device__ float g_x2[MM*CC];      // after attn residual
__device__ float g_h2[MM*CC];      // LN2 out (tf32-rounded)
__device__ float g_mlp[MM*MLPD];   // gelu(...) (tf32-rounded)
__device__ float g_wqkv_r[C3*CC];
__device__ float g_wproj_r[CC*CC];
__device__ float g_w1_r[MLPD*CC];
__device__ float g_w2_r[CC*MLPD];

__device__ __forceinline__ float rna_tf32(float x) {
    uint32_t u;
    asm("cvt.rna.tf32.f32 %0, %1;" : "=r"(u) : "f"(x));
    return __uint_as_float(u);
}

#define CP_ASYNC16(dst, src) \
    asm volatile("cp.async.ca.shared.global [%0], [%1], 16;" :: "r"(dst), "l"(src))
#define CP_COMMIT() asm volatile("cp.async.commit_group;")
#define CP_WAIT(n)  asm volatile("cp.async.wait_group %0;" :: "n"(n))

#define LDMATRIX_X4(r0, r1, r2, r3, addr) \
    asm volatile("ldmatrix.sync.aligned.m8n8.x4.shared.b16 {%0,%1,%2,%3}, [%4];" \
                 : "=r"(r0), "=r"(r1), "=r"(r2), "=r"(r3) : "r"(addr))

#define MMA_TF32(c0, c1, c2, c3, a0, a1, a2, a3, b0, b1) \
    asm volatile("mma.sync.aligned.m16n8k8.row.col.f32.tf32.tf32.f32 " \
                 "{%0,%1,%2,%3}, {%4,%5,%6,%7}, {%8,%9}, {%0,%1,%2,%3};" \
                 : "+f"(c0), "+f"(c1), "+f"(c2), "+f"(c3) \
                 : "r"(a0), "r"(a1), "r"(a2), "r"(a3), "r"(b0), "r"(b1))

// ---------------- weight rounding ----------------
__global__ void round_tf32_kernel(const float* __restrict__ in,
                                  float* __restrict__ out, int n4) {
    int i = blockIdx.x * blockDim.x + threadIdx.x;
    if (i < n4) {
        float4 v = ((const float4*)in)[i];
        v.x = rna_tf32(v.x); v.y = rna_tf32(v.y);
        v.z = rna_tf32(v.z); v.w = rna_tf32(v.w);
        ((float4*)out)[i] = v;
    }
}

// ---------------- fused (x+pos) + LayerNorm (output tf32-rounded) ----------------
__global__ void addpos_ln_kernel(const float* __restrict__ x,
                                 const float* __restrict__ pos,
                                 const float* __restrict__ g,
                                 const float* __restrict__ b,
                                 float* __restrict__ x1out,
                                 float* __restrict__ hout) {
    int row = blockIdx.x;
    int t = threadIdx.x;
    const float* xr = x + row * CC;
    float v[4];
#pragma unroll
    for (int i = 0; i < 4; i++) {
        int c = t + i * 256;
        float val = xr[c];
        if (pos) val += pos[row * CC + c];
        v[i] = val;
        if (x1out) x1out[row * CC + c] = val;
    }
    __shared__ float sred[256];
    float s = v[0] + v[1] + v[2] + v[3];
    sred[t] = s; __syncthreads();
    for (int o = 128; o > 0; o >>= 1) { if (t < o) sred[t] += sred[t + o]; __syncthreads(); }
    float mean = sred[0] * (1.0f / CC);
    __syncthreads();
    float sq = 0.f;
#pragma unroll
    for (int i = 0; i < 4; i++) { float d = v[i] - mean; sq += d * d; }
    sred[t] = sq; __syncthreads();
    for (int o = 128; o > 0; o >>= 1) { if (t < o) sred[t] += sred[t + o]; __syncthreads(); }
    float rstd = rsqrtf(sred[0] * (1.0f / CC) + 1e-5f);
#pragma unroll
    for (int i = 0; i < 4; i++) {
        int c = t + i * 256;
        hout[row * CC + c] = rna_tf32((v[i] - mean) * rstd * g[c] + b[c]);
    }
}

// ---------------- TF32 tensor-core GEMM (unchanged from round 2) ----------------
__global__ void __launch_bounds__(256)
gemm_tf32_kernel(const float* __restrict__ A, const float* __restrict__ B,
                 const float* __restrict__ bias, const float* __restrict__ res,
                 float* __restrict__ Cout, int M, int Ncols, int K,
                 int act, int rnd) {
    extern __shared__ float smf[];
    uint32_t smbase = (uint32_t)__cvta_generic_to_shared(smf);
    const int tid = threadIdx.x;
    const int lane = tid & 31;
    const int warp = tid >> 5;
    const int warp_m = warp & 1;
    const int warp_n = warp >> 1;
    const int bm = blockIdx.y * 128;
    const int bn = blockIdx.x * 128;

    const int a_lrow = lane & 15;
    const int a_lch  = lane >> 4;
    const int b_nrow = (lane & 7) + ((lane >> 4) << 3);
    const int b_kc   = (lane & 8) >> 3;

    float acc[4][4][4];
#pragma unroll
    for (int i = 0; i < 4; i++)
#pragma unroll
        for (int j = 0; j < 4; j++)
#pragma unroll
            for (int r = 0; r < 4; r++) acc[i][j][r] = 0.f;

    const int Ksteps = K >> 5;

    auto load_tile = [&](int s, int kk) {
        uint32_t a_base = smbase + s * 16384;
        uint32_t b_base = smbase + 32768 + s * 16384;
#pragma unroll
        for (int i = 0; i < 4; i++) {
            int id = tid + i * 256;
            int row = id >> 3, ch = id & 7;
            const float* srcA = A + (size_t)(bm + row) * K + kk + ch * 4;
            uint32_t dstA = a_base + row * 128 + (((ch ^ (row & 7))) << 4);
            CP_ASYNC16(dstA, srcA);
        }
#pragma unroll
        for (int i = 0; i < 4; i++) {
            int id = tid + i * 256;
            int row = id >> 3, ch = id & 7;
            const float* srcB = B + (size_t)(bn + row) * K + kk + ch * 4;
            uint32_t dstB = b_base + row * 128 + (((ch ^ (row & 7))) << 4);
            CP_ASYNC16(dstB, srcB);
        }
    };

    load_tile(0, 0);
    CP_COMMIT();

    for (int s = 0; s < Ksteps; s++) {
        int buf = s & 1;
        if (s + 1 < Ksteps) {
            load_tile(buf ^ 1, (s + 1) << 5);
            CP_COMMIT();
            CP_WAIT(1);
        } else {
            CP_WAIT(0);
        }
        __syncthreads();

        uint32_t a_base = smbase + buf * 16384;
        uint32_t b_base = smbase + 32768 + buf * 16384;

#pragma unroll
        for (int ks = 0; ks < 4; ks++) {
            uint32_t af[4][4];
#pragma unroll
            for (int mt = 0; mt < 4; mt++) {
                int m = warp_m * 64 + mt * 16 + a_lrow;
                int chunk = ks * 2 + a_lch;
                uint32_t addr = a_base + m * 128 + ((chunk ^ (m & 7)) << 4);
                LDMATRIX_X4(af[mt][0], af[mt][1], af[mt][2], af[mt][3], addr);
            }
            uint32_t bf[2][4];
#pragma unroll
            for (int p = 0; p < 2; p++) {
                int n = warp_n * 32 + p * 16 + b_nrow;
                int chunk = ks * 2 + b_kc;
                uint32_t addr = b_base + n * 128 + ((chunk ^ (n & 7)) << 4);
                LDMATRIX_X4(bf[p][0], bf[p][1], bf[p][2], bf[p][3], addr);
            }
#pragma unroll
            for (int mt = 0; mt < 4; mt++)
#pragma unroll
                for (int nt = 0; nt < 4; nt++) {
                    uint32_t b0 = bf[nt >> 1][(nt & 1) * 2];
                    uint32_t b1 = bf[nt >> 1][(nt & 1) * 2 + 1];
                    MMA_TF32(acc[mt][nt][0], acc[mt][nt][1], acc[mt][nt][2], acc[mt][nt][3],
                             af[mt][0], af[mt][1], af[mt][2], af[mt][3], b0, b1);
                }
        }
        __syncthreads();
    }

    const int gid = lane >> 2;
    const int tig = lane & 3;
#pragma unroll
    for (int mt = 0; mt < 4; mt++) {
#pragma unroll
        for (int nt = 0; nt < 4; nt++) {
            int col = bn + warp_n * 32 + nt * 8 + tig * 2;
            float bi0 = bias[col], bi1 = bias[col + 1];
#pragma unroll
            for (int half = 0; half < 2; half++) {
                int row = bm + warp_m * 64 + mt * 16 + gid + half * 8;
                float v0 = acc[mt][nt][half * 2 + 0] + bi0;
                float v1 = acc[mt][nt][half * 2 + 1] + bi1;
                if (act == 1) {
                    v0 = 0.5f * v0 * (1.0f + erff(v0 * 0.70710678118654752f));
                    v1 = 0.5f * v1 * (1.0f + erff(v1 * 0.70710678118654752f));
                }
                if (res) {
                    v0 += res[(size_t)row * Ncols + col];
                    v1 += res[(size_t)row * Ncols + col + 1];
                }
                if (rnd) { v0 = rna_tf32(v0); v1 = rna_tf32(v1); }
                float2 ov = make_float2(v0, v1);
                *(float2*)&Cout[(size_t)row * Ncols + col] = ov;
            }
        }
    }
}

// ---------------- LoRA ----------------
__global__ void lora_afterA_kernel(const float* __restrict__ h,
                                   const float* __restrict__ Amat,
                                   float* __restrict__ outA) {
    int m = blockIdx.x;
    int t = threadIdx.x;
    float acc[8] = {0, 0, 0, 0, 0, 0, 0, 0};
    const float* hr = h + m * CC;
    for (int c = t; c < CC; c += 256) {
        float hv = hr[c];
#pragma unroll
        for (int r = 0; r < 8; r++) acc[r] = fmaf(hv, Amat[r * CC + c], acc[r]);
    }
#pragma unroll
    for (int r = 0; r < 8; r++)
#pragma unroll
        for (int o = 16; o > 0; o >>= 1)
            acc[r] += __shfl_down_sync(0xffffffffu, acc[r], o);
    __shared__ float sw[8][8];
    int warp = t >> 5, lane = t & 31;
    if (lane == 0) {
#pragma unroll
        for (int r = 0; r < 8; r++) sw[warp][r] = acc[r];
    }
    __syncthreads();
    if (t < 8) {
        float s = 0.f;
#pragma unroll
        for (int w = 0; w < 8; w++) s += sw[w][t];
        outA[m * 8 + t] = s;
    }
}

__global__ void lora_apply_kernel(const float* __restrict__ afterA,
                                  const float* __restrict__ Bm,
                                  float* __restrict__ qkv) {
    int idx = blockIdx.x * blockDim.x + threadIdx.x;
    int m = idx >> 10;
    int c = idx & 1023;
    const float* a = afterA + m * 8;
    float dq = 0.f, dv = 0.f;
#pragma unroll
    for (int r = 0; r < 4; r++) {
        dq = fmaf(a[r],     Bm[c * 4 + r],        dq);
        dv = fmaf(a[4 + r], Bm[(CC + c) * 4 + r], dv);
    }
    qkv[(size_t)m * C3 + c]          += 0.25f * dq;
    qkv[(size_t)m * C3 + 2 * CC + c] += 0.25f * dv;
}

// ---------------- tensor-core flash attention (tf32 MMA, online softmax) ----------------
// grid (N/64, H, B), 128 threads = 4 warps; warp owns 16 query rows.
// smem (floats): Qs [0,4096) Ks [4096,8192) Vt [8192,12288) Ps [12288,16384)
__global__ void __launch_bounds__(128)
attn_tc_kernel(const float* __restrict__ qkv, float* __restrict__ out) {
    extern __shared__ float sm[];
    uint32_t smb = (uint32_t)__cvta_generic_to_shared(sm);
    const int b = blockIdx.z, h = blockIdx.y;
    const int q0 = blockIdx.x * 64;
    const int tid = threadIdx.x;
    const int lane = tid & 31;
    const int w = tid >> 5;
    const int gid = lane >> 2, tig = lane & 3;
    const int arow = lane & 15, alch = lane >> 4;
    const int b_nrow = (lane & 7) + ((lane >> 4) << 3);
    const int b_kc = (lane & 8) >> 3;
    const float scale = 0.125f;   // 1/sqrt(64)

    // ---- stage Q (scaled + tf32-rounded), 256B swizzled rows ----
    for (int i = tid; i < 1024; i += 128) {
        int r = i >> 4, c = i & 15;
        const float* src = qkv + ((size_t)(b * NN + q0 + r)) * C3 + h * DH + c * 4;
        float4 v = *(const float4*)src;
        v.x = rna_tf32(v.x * scale); v.y = rna_tf32(v.y * scale);
        v.z = rna_tf32(v.z * scale); v.w = rna_tf32(v.w * scale);
        *(float4*)&sm[(r << 6) + ((c ^ (r & 7)) << 2)] = v;
    }

    float acco[8][4];
#pragma unroll
    for (int nt = 0; nt < 8; nt++)
#pragma unroll
        for (int j = 0; j < 4; j++) acco[nt][j] = 0.f;
    float m0 = -1e30f, m1 = -1e30f, l0 = 0.f, l1 = 0.f;

    for (int kt = 0; kt < NN; kt += 64) {
        // ---- stage K (natural) + V (transposed, lane-rotated to dodge conflicts) ----
        for (int i = tid; i < 1024; i += 128) {
            int r = i >> 4, c = i & 15;
            const float* kp = qkv + ((size_t)(b * NN + kt + r)) * C3 + CC + h * DH + c * 4;
            float4 kv = *(const float4*)kp;
            kv.x = rna_tf32(kv.x); kv.y = rna_tf32(kv.y);
            kv.z = rna_tf32(kv.z); kv.w = rna_tf32(kv.w);
            *(float4*)&sm[4096 + (r << 6) + ((c ^ (r & 7)) << 2)] = kv;

            float4 vv = *(const float4*)(kp + CC);
            float a0 = rna_tf32(vv.x), a1 = rna_tf32(vv.y);
            float a2 = rna_tf32(vv.z), a3 = rna_tf32(vv.w), t;
            if (lane & 1) { t = a0; a0 = a1; a1 = a2; a2 = a3; a3 = t; }
            if (lane & 2) { t = a0; a0 = a2; a2 = t; t = a1; a1 = a3; a3 = t; }
            // slot j now holds component (j+lane)&3 -> store to d = c*4 + (j+lane)&3
            int rq = r >> 2, rm = r & 3;
#pragma unroll
            for (int j = 0; j < 4; j++) {
                int d = c * 4 + ((j + lane) & 3);
                float val = (j == 0) ? a0 : (j == 1) ? a1 : (j == 2) ? a2 : a3;
                sm[8192 + (d << 6) + ((rq ^ (d & 7)) << 2) + rm] = val;
            }
        }
        __syncthreads();

        // ---- S = Q K^T (warp: 16 q-rows x 64 keys) ----
        float accs[8][4];
#pragma unroll
        for (int nt = 0; nt < 8; nt++)
#pragma unroll
            for (int j = 0; j < 4; j++) accs[nt][j] = 0.f;

#pragma unroll
        for (int ks = 0; ks < 8; ks++) {
            uint32_t a0, a1, a2, a3;
            int qr = w * 16 + arow;
            uint32_t aaddr = smb + (qr << 8) + ((((ks << 1) + alch) ^ (arow & 7)) << 4);
            LDMATRIX_X4(a0, a1, a2, a3, aaddr);
#pragma unroll
            for (int p = 0; p < 4; p++) {
                int br = p * 16 + b_nrow;
                uint32_t baddr = smb + 16384 + (br << 8) + ((((ks << 1) + b_kc) ^ (br & 7)) << 4);
                uint32_t f0, f1, f2, f3;
                LDMATRIX_X4(f0, f1, f2, f3, baddr);
                MMA_TF32(accs[2*p][0], accs[2*p][1], accs[2*p][2], accs[2*p][3],
                         a0, a1, a2, a3, f0, f1);
                MMA_TF32(accs[2*p+1][0], accs[2*p+1][1], accs[2*p+1][2], accs[2*p+1][3],
                         a0, a1, a2, a3, f2, f3);
            }
        }

        // ---- online softmax ----
        float mx0 = -1e30f, mx1 = -1e30f;
#pragma unroll
        for (int nt = 0; nt < 8; nt++) {
            mx0 = fmaxf(mx0, fmaxf(accs[nt][0], accs[nt][1]));
            mx1 = fmaxf(mx1, fmaxf(accs[nt][2], accs[nt][3]));
        }
        mx0 = fmaxf(mx0, __shfl_xor_sync(0xffffffffu, mx0, 1));
        mx0 = fmaxf(mx0, __shfl_xor_sync(0xffffffffu, mx0, 2));
        mx1 = fmaxf(mx1, __shfl_xor_sync(0xffffffffu, mx1, 1));
        mx1 = fmaxf(mx1, __shfl_xor_sync(0xffffffffu, mx1, 2));
        float mn0 = fmaxf(m0, mx0), mn1 = fmaxf(m1, mx1);
        float cr0 = __expf(m0 - mn0), cr1 = __expf(m1 - mn1);
        float s0 = 0.f, s1 = 0.f;
#pragma unroll
        for (int nt = 0; nt < 8; nt++) {
            float p0 = rna_tf32(__expf(accs[nt][0] - mn0));
            float p1 = rna_tf32(__expf(accs[nt][1] - mn0));
            float p2 = rna_tf32(__expf(accs[nt][2] - mn1));
            float p3 = rna_tf32(__expf(accs[nt][3] - mn1));
            accs[nt][0] = p0; accs[nt][1] = p1; accs[nt][2] = p2; accs[nt][3] = p3;
            s0 += p0 + p1; s1 += p2 + p3;
        }
        s0 += __shfl_xor_sync(0xffffffffu, s0, 1);
        s0 += __shfl_xor_sync(0xffffffffu, s0, 2);
        s1 += __shfl_xor_sync(0xffffffffu, s1, 1);
        s1 += __shfl_xor_sync(0xffffffffu, s1, 2);
        l0 = l0 * cr0 + s0; l1 = l1 * cr1 + s1;
        m0 = mn0; m1 = mn1;
#pragma unroll
        for (int nt = 0; nt < 8; nt++) {
            acco[nt][0] *= cr0; acco[nt][1] *= cr0;
            acco[nt][2] *= cr1; acco[nt][3] *= cr1;
        }

        // ---- store P to per-warp region ----
        {
            int base = 12288 + w * 1024;
#pragma unroll
            for (int nt = 0; nt < 8; nt++) {
                int ch = nt * 2 + (tig >> 1);
                int off  = base + (gid << 6) + ((ch ^ (gid & 7)) << 2);
                int offh = base + ((gid + 8) << 6) + ((ch ^ (gid & 7)) << 2);
                sm[off  + ((tig * 2) & 3)]     = accs[nt][0];
                sm[off  + ((tig * 2 + 1) & 3)] = accs[nt][1];
                sm[offh + ((tig * 2) & 3)]     = accs[nt][2];
                sm[offh + ((tig * 2 + 1) & 3)] = accs[nt][3];
            }
        }
        __syncwarp();

        // ---- O += P V ----
#pragma unroll
        for (int ks = 0; ks < 8; ks++) {
            uint32_t a0, a1, a2, a3;
            uint32_t aaddr = smb + 49152 + w * 4096 + (arow << 8)
                           + ((((ks << 1) + alch) ^ (arow & 7)) << 4);
            LDMATRIX_X4(a0, a1, a2, a3, aaddr);
#pragma unroll
            for (int p = 0; p < 4; p++) {
                int br = p * 16 + b_nrow;   // dh rows of Vt
                uint32_t baddr = smb + 32768 + (br << 8)
                               + ((((ks << 1) + b_kc) ^ (br & 7)) << 4);
                uint32_t f0, f1, f2, f3;
                LDMATRIX_X4(f0, f1, f2, f3, baddr);
                MMA_TF32(acco[2*p][0], acco[2*p][1], acco[2*p][2], acco[2*p][3],
                         a0, a1, a2, a3, f0, f1);
                MMA_TF32(acco[2*p+1][0], acco[2*p+1][1], acco[2*p+1][2], acco[2*p+1][3],
                         a0, a1, a2, a3, f2, f3);
            }
        }
        __syncthreads();
    }

    // ---- epilogue ----
    float inv0 = 1.f / l0, inv1 = 1.f / l1;
#pragma unroll
    for (int nt = 0; nt < 8; nt++) {
        int col = h * DH + nt * 8 + tig * 2;
        size_t r0 = (size_t)(b * NN + q0 + w * 16 + gid) * CC + col;
        float2 v0 = make_float2(rna_tf32(acco[nt][0] * inv0), rna_tf32(acco[nt][1] * inv0));
        *(float2*)&out[r0] = v0;
        size_t r1 = (size_t)(b * NN + q0 + w * 16 + gid + 8) * CC + col;
        float2 v1 = make_float2(rna_tf32(acco[nt][2] * inv1), rna_tf32(acco[nt][3] * inv1));
        *(float2*)&out[r1] = v1;
    }
}

// ---------------- launch ----------------
extern "C" void kernel_launch(void* const* d_in, const int* in_sizes, int n_in,
                              void* d_out, int out_size) {
    const float* x      = (const float*)d_in[0];
    const float* pos    = (const float*)d_in[1];
    const float* Wqkv   = (const float*)d_in[2];
    const float* b_qkv  = (const float*)d_in[3];
    const float* lora_A = (const float*)d_in[4];
    const float* lora_B = (const float*)d_in[5];
    const float* Wproj  = (const float*)d_in[6];
    const float* b_proj = (const float*)d_in[7];
    const float* ln1_g  = (const float*)d_in[8];
    const float* ln1_b  = (const float*)d_in[9];
    const float* ln2_g  = (const float*)d_in[10];
    const float* ln2_b  = (const float*)d_in[11];
    const float* W1     = (const float*)d_in[12];
    const float* b1     = (const float*)d_in[13];
    const float* W2     = (const float*)d_in[14];
    const float* b2     = (const float*)d_in[15];
    float* out = (float*)d_out;

    float *p_x1, *p_h, *p_qkv, *p_afterA, *p_attn, *p_x2, *p_h2, *p_mlp;
    float *p_wqkv, *p_wproj, *p_w1, *p_w2;
    cudaGetSymbolAddress((void**)&p_x1, g_x1);
    cudaGetSymbolAddress((void**)&p_h, g_h);
    cudaGetSymbolAddress((void**)&p_qkv, g_qkv);
    cudaGetSymbolAddress((void**)&p_afterA, g_afterA);
    cudaGetSymbolAddress((void**)&p_attn, g_attn);
    cudaGetSymbolAddress((void**)&p_x2, g_x2);
    cudaGetSymbolAddress((void**)&p_h2, g_h2);
    cudaGetSymbolAddress((void**)&p_mlp, g_mlp);
    cudaGetSymbolAddress((void**)&p_wqkv, g_wqkv_r);
    cudaGetSymbolAddress((void**)&p_wproj, g_wproj_r);
    cudaGetSymbolAddress((void**)&p_w1, g_w1_r);
    cudaGetSymbolAddress((void**)&p_w2, g_w2_r);

    static bool attr_set = false;
    if (!attr_set) {
        cudaFuncSetAttribute(gemm_tf32_kernel,
                             cudaFuncAttributeMaxDynamicSharedMemorySize, 65536);
        cudaFuncSetAttribute(attn_tc_kernel,
                             cudaFuncAttributeMaxDynamicSharedMemorySize, 65536);
        attr_set = true;
    }

    // 0) round weights to tf32
    round_tf32_kernel<<<(C3 * CC / 4 + 255) / 256, 256>>>(Wqkv, p_wqkv, C3 * CC / 4);
    round_tf32_kernel<<<(CC * CC / 4 + 255) / 256, 256>>>(Wproj, p_wproj, CC * CC / 4);
    round_tf32_kernel<<<(MLPD * CC / 4 + 255) / 256, 256>>>(W1, p_w1, MLPD * CC / 4);
    round_tf32_kernel<<<(CC * MLPD / 4 + 255) / 256, 256>>>(W2, p_w2, CC * MLPD / 4);

    // 1) x1 = x + pos ; h = LN1(x1) (rounded)
    addpos_ln_kernel<<<MM, 256>>>(x, pos, ln1_g, ln1_b, p_x1, p_h);

    // 2) qkv = h @ Wqkv^T + b_qkv
    gemm_tf32_kernel<<<dim3(C3 / 128, MM / 128), 256, 65536>>>(
        p_h, p_wqkv, b_qkv, nullptr, p_qkv, MM, C3, CC, 0, 0);

    // 3) LoRA
    lora_afterA_kernel<<<MM, 256>>>(p_h, lora_A, p_afterA);
    lora_apply_kernel<<<(MM * CC) / 256, 256>>>(p_afterA, lora_B, p_qkv);

    // 4) attention (tensor-core flash)
    attn_tc_kernel<<<dim3(NN / 64, HH, BB), 128, 65536>>>(p_qkv, p_attn);

    // 5) x2 = x1 + attn @ Wproj^T + b_proj
    gemm_tf32_kernel<<<dim3(CC / 128, MM / 128), 256, 65536>>>(
        p_attn, p_wproj, b_proj, p_x1, p_x2, MM, CC, CC, 0, 0);

    // 6) h2 = LN2(x2) (rounded)
    addpos_ln_kernel<<<MM, 256>>>(p_x2, nullptr, ln2_g, ln2_b, nullptr, p_h2);

    // 7) mlp = gelu(h2 @ W1^T + b1) (rounded)
    gemm_tf32_kernel<<<dim3(MLPD / 128, MM / 128), 256, 65536>>>(
        p_h2, p_w1, b1, nullptr, p_mlp, MM, MLPD, CC, 1, 1);

    // 8) out = x2 + mlp @ W2^T + b2
    gemm_tf32_kernel<<<dim3(CC / 128, MM / 128), 256, 65536>>>(
        p_mlp, p_w2, b2, p_x2, out, MM, CC, MLPD, 0, 0);
}

// round 4
// speedup vs baseline: 6.5936x; 1.9851x over previous
#include <cuda_runtime.h>
#include <cuda_fp16.h>
#include <math.h>
#include <stdint.h>

// Problem constants
#define BB 2
#define NN 2048
#define CC 1024
#define HH 16
#define DH 64
#define MLPD 4096
#define MM (BB*NN)          // 4096 tokens
#define C3 (3*CC)           // 3072

// ---------------- scratch (static device globals; no allocation) ----------------
__device__ float  g_x1[MM*CC];       // x + pos (fp32 residual)
__device__ float  g_x2[MM*CC];       // after attn residual (fp32)
__device__ __half g_h[MM*CC];        // LN1 out
__device__ __half g_qkv[MM*C3];      // qkv (+lora)
__device__ float  g_afterA[MM*8];    // h @ lora_A^T
__device__ __half g_attn[MM*CC];     // attention out
__device__ __half g_h2[MM*CC];       // LN2 out
__device__ __half g_mlp[MM*MLPD];    // gelu(...)
__device__ __half g_wqkv_h[C3*CC];
__device__ __half g_wproj_h[CC*CC];
__device__ __half g_w1_h[MLPD*CC];
__device__ __half g_w2_h[CC*MLPD];

#define CP_ASYNC16(dst, src) \
    asm volatile("cp.async.ca.shared.global [%0], [%1], 16;" :: "r"(dst), "l"(src))
#define CP_COMMIT() asm volatile("cp.async.commit_group;")
#define CP_WAIT(n)  asm volatile("cp.async.wait_group %0;" :: "n"(n))

#define LDMATRIX_X4(r0, r1, r2, r3, addr) \
    asm volatile("ldmatrix.sync.aligned.m8n8.x4.shared.b16 {%0,%1,%2,%3}, [%4];" \
                 : "=r"(r0), "=r"(r1), "=r"(r2), "=r"(r3) : "r"(addr))
#define LDMATRIX_X4_T(r0, r1, r2, r3, addr) \
    asm volatile("ldmatrix.sync.aligned.m8n8.x4.trans.shared.b16 {%0,%1,%2,%3}, [%4];" \
                 : "=r"(r0), "=r"(r1), "=r"(r2), "=r"(r3) : "r"(addr))

#define MMA_F16(c0, c1, c2, c3, a0, a1, a2, a3, b0, b1) \
    asm volatile("mma.sync.aligned.m16n8k16.row.col.f32.f16.f16.f32 " \
                 "{%0,%1,%2,%3}, {%4,%5,%6,%7}, {%8,%9}, {%0,%1,%2,%3};" \
                 : "+f"(c0), "+f"(c1), "+f"(c2), "+f"(c3) \
                 : "r"(a0), "r"(a1), "r"(a2), "r"(a3), "r"(b0), "r"(b1))

// ---------------- fp32 -> fp16 weight conversion ----------------
__global__ void f2h_kernel(const float* __restrict__ in,
                           __half* __restrict__ out, int n8) {
    int i = blockIdx.x * blockDim.x + threadIdx.x;
    if (i < n8) {
        float4 a = ((const float4*)in)[2 * i];
        float4 b = ((const float4*)in)[2 * i + 1];
        __half2 h[4];
        h[0] = __floats2half2_rn(a.x, a.y);
        h[1] = __floats2half2_rn(a.z, a.w);
        h[2] = __floats2half2_rn(b.x, b.y);
        h[3] = __floats2half2_rn(b.z, b.w);
        ((uint4*)out)[i] = *(uint4*)h;
    }
}

// ---------------- fused (x+pos) + LayerNorm -> fp16 ----------------
__global__ void addpos_ln_kernel(const float* __restrict__ x,
                                 const float* __restrict__ pos,
                                 const float* __restrict__ g,
                                 const float* __restrict__ b,
                                 float* __restrict__ x1out,
                                 __half* __restrict__ hout) {
    int row = blockIdx.x;
    int t = threadIdx.x;
    const float* xr = x + row * CC;
    float v[4];
#pragma unroll
    for (int i = 0; i < 4; i++) {
        int c = t + i * 256;
        float val = xr[c];
        if (pos) val += pos[row * CC + c];
        v[i] = val;
        if (x1out) x1out[row * CC + c] = val;
    }
    __shared__ float sred[256];
    float s = v[0] + v[1] + v[2] + v[3];
    sred[t] = s; __syncthreads();
    for (int o = 128; o > 0; o >>= 1) { if (t < o) sred[t] += sred[t + o]; __syncthreads(); }
    float mean = sred[0] * (1.0f / CC);
    __syncthreads();
    float sq = 0.f;
#pragma unroll
    for (int i = 0; i < 4; i++) { float d = v[i] - mean; sq += d * d; }
    sred[t] = sq; __syncthreads();
    for (int o = 128; o > 0; o >>= 1) { if (t < o) sred[t] += sred[t + o]; __syncthreads(); }
    float rstd = rsqrtf(sred[0] * (1.0f / CC) + 1e-5f);
#pragma unroll
    for (int i = 0; i < 4; i++) {
        int c = t + i * 256;
        hout[row * CC + c] = __float2half_rn((v[i] - mean) * rstd * g[c] + b[c]);
    }
}

// ---------------- fp16 tensor-core GEMM: C = A[M,K] * B[N,K]^T + bias (+gelu)(+res) ----------------
// 128x128x64 tiles, 256 threads = 8 warps (2m x 4n), warp tile 64x32.
// 2-stage cp.async, 128B-row swizzle, ldmatrix, mma.m16n8k16.
__global__ void __launch_bounds__(256)
gemm_f16_kernel(const __half* __restrict__ A, const __half* __restrict__ B,
                const float* __restrict__ bias, const float* __restrict__ res,
                float* __restrict__ outf, __half* __restrict__ outh,
                int M, int Ncols, int K, int act) {
    extern __shared__ char smc[];
    uint32_t smbase = (uint32_t)__cvta_generic_to_shared(smc);
    // stages: A0 [0,16K) A1 [16K,32K) B0 [32K,48K) B1 [48K,64K)
    const int tid = threadIdx.x;
    const int lane = tid & 31;
    const int warp = tid >> 5;
    const int warp_m = warp & 1;
    const int warp_n = warp >> 1;
    const int bm = blockIdx.y * 128;
    const int bn = blockIdx.x * 128;

    const int a_lrow = lane & 15;
    const int a_lch  = lane >> 4;
    const int b_nrow = (lane & 7) + ((lane >> 4) << 3);
    const int b_kc   = (lane & 8) >> 3;

    float acc[4][4][4];
#pragma unroll
    for (int i = 0; i < 4; i++)
#pragma unroll
        for (int j = 0; j < 4; j++)
#pragma unroll
            for (int r = 0; r < 4; r++) acc[i][j][r] = 0.f;

    const int Ksteps = K >> 6;   // K/64

    auto load_tile = [&](int s, int kk) {
        uint32_t a_base = smbase + s * 16384;
        uint32_t b_base = smbase + 32768 + s * 16384;
#pragma unroll
        for (int i = 0; i < 4; i++) {
            int id = tid + i * 256;           // 0..1023
            int row = id >> 3, ch = id & 7;
            const __half* srcA = A + (size_t)(bm + row) * K + kk + ch * 8;
            uint32_t dstA = a_base + row * 128 + ((ch ^ (row & 7)) << 4);
            CP_ASYNC16(dstA, srcA);
        }
#pragma unroll
        for (int i = 0; i < 4; i++) {
            int id = tid + i * 256;
            int row = id >> 3, ch = id & 7;
            const __half* srcB = B + (size_t)(bn + row) * K + kk + ch * 8;
            uint32_t dstB = b_base + row * 128 + ((ch ^ (row & 7)) << 4);
            CP_ASYNC16(dstB, srcB);
        }
    };

    load_tile(0, 0);
    CP_COMMIT();

    for (int s = 0; s < Ksteps; s++) {
        int buf = s & 1;
        if (s + 1 < Ksteps) {
            load_tile(buf ^ 1, (s + 1) << 6);
            CP_COMMIT();
            CP_WAIT(1);
        } else {
            CP_WAIT(0);
        }
        __syncthreads();

        uint32_t a_base = smbase + buf * 16384;
        uint32_t b_base = smbase + 32768 + buf * 16384;

#pragma unroll
        for (int ks = 0; ks < 4; ks++) {
            uint32_t af[4][4];
#pragma unroll
            for (int mt = 0; mt < 4; mt++) {
                int m = warp_m * 64 + mt * 16 + a_lrow;
                int chunk = ks * 2 + a_lch;
                uint32_t addr = a_base + m * 128 + ((chunk ^ (m & 7)) << 4);
                LDMATRIX_X4(af[mt][0], af[mt][1], af[mt][2], af[mt][3], addr);
            }
            uint32_t bf[2][4];
#pragma unroll
            for (int p = 0; p < 2; p++) {
                int n = warp_n * 32 + p * 16 + b_nrow;
                int chunk = ks * 2 + b_kc;
                uint32_t addr = b_base + n * 128 + ((chunk ^ (n & 7)) << 4);
                LDMATRIX_X4(bf[p][0], bf[p][1], bf[p][2], bf[p][3], addr);
            }
#pragma unroll
            for (int mt = 0; mt < 4; mt++)
#pragma unroll
                for (int nt = 0; nt < 4; nt++) {
                    uint32_t b0 = bf[nt >> 1][(nt & 1) * 2];
                    uint32_t b1 = bf[nt >> 1][(nt & 1) * 2 + 1];
                    MMA_F16(acc[mt][nt][0], acc[mt][nt][1], acc[mt][nt][2], acc[mt][nt][3],
                            af[mt][0], af[mt][1], af[mt][2], af[mt][3], b0, b1);
                }
        }
        __syncthreads();
    }

    const int gid = lane >> 2;
    const int tig = lane & 3;
#pragma unroll
    for (int mt = 0; mt < 4; mt++) {
#pragma unroll
        for (int nt = 0; nt < 4; nt++) {
            int col = bn + warp_n * 32 + nt * 8 + tig * 2;
            float bi0 = bias[col], bi1 = bias[col + 1];
#pragma unroll
            for (int half_i = 0; half_i < 2; half_i++) {
                int row = bm + warp_m * 64 + mt * 16 + gid + half_i * 8;
                float v0 = acc[mt][nt][half_i * 2 + 0] + bi0;
                float v1 = acc[mt][nt][half_i * 2 + 1] + bi1;
                if (act == 1) {
                    v0 = 0.5f * v0 * (1.0f + erff(v0 * 0.70710678118654752f));
                    v1 = 0.5f * v1 * (1.0f + erff(v1 * 0.70710678118654752f));
                }
                if (res) {
                    v0 += res[(size_t)row * Ncols + col];
                    v1 += res[(size_t)row * Ncols + col + 1];
                }
                if (outh) {
                    __half2 hv = __floats2half2_rn(v0, v1);
                    *(__half2*)&outh[(size_t)row * Ncols + col] = hv;
                } else {
                    float2 ov = make_float2(v0, v1);
                    *(float2*)&outf[(size_t)row * Ncols + col] = ov;
                }
            }
        }
    }
}

// ---------------- LoRA ----------------
__global__ void lora_afterA_kernel(const __half* __restrict__ h,
                                   const float* __restrict__ Amat,
                                   float* __restrict__ outA) {
    int m = blockIdx.x;
    int t = threadIdx.x;
    float acc[8] = {0, 0, 0, 0, 0, 0, 0, 0};
    const __half* hr = h + (size_t)m * CC;
    for (int c = t; c < CC; c += 256) {
        float hv = __half2float(hr[c]);
#pragma unroll
        for (int r = 0; r < 8; r++) acc[r] = fmaf(hv, Amat[r * CC + c], acc[r]);
    }
#pragma unroll
    for (int r = 0; r < 8; r++)
#pragma unroll
        for (int o = 16; o > 0; o >>= 1)
            acc[r] += __shfl_down_sync(0xffffffffu, acc[r], o);
    __shared__ float sw[8][8];
    int warp = t >> 5, lane = t & 31;
    if (lane == 0) {
#pragma unroll
        for (int r = 0; r < 8; r++) sw[warp][r] = acc[r];
    }
    __syncthreads();
    if (t < 8) {
        float s = 0.f;
#pragma unroll
        for (int w = 0; w < 8; w++) s += sw[w][t];
        outA[m * 8 + t] = s;
    }
}

__global__ void lora_apply_kernel(const float* __restrict__ afterA,
                                  const float* __restrict__ Bm,
                                  __half* __restrict__ qkv) {
    int idx = blockIdx.x * blockDim.x + threadIdx.x;
    int m = idx >> 10;
    int c = idx & 1023;
    const float* a = afterA + m * 8;
    float dq = 0.f, dv = 0.f;
#pragma unroll
    for (int r = 0; r < 4; r++) {
        dq = fmaf(a[r],     Bm[c * 4 + r],        dq);
        dv = fmaf(a[4 + r], Bm[(CC + c) * 4 + r], dv);
    }
    size_t iq = (size_t)m * C3 + c;
    size_t iv = (size_t)m * C3 + 2 * CC + c;
    qkv[iq] = __float2half_rn(__half2float(qkv[iq]) + 0.25f * dq);
    qkv[iv] = __float2half_rn(__half2float(qkv[iv]) + 0.25f * dv);
}

// ---------------- fp16 tensor-core flash attention ----------------
// grid (N/64, H, B), 128 threads = 4 warps; warp owns 16 query rows.
// smem bytes: Q [0,8K) K0 [8K,16K) K1 [16K,24K) V0 [24K,32K) V1 [32K,40K) P [40K,48K)
__global__ void __launch_bounds__(128)
attn_f16_kernel(const __half* __restrict__ qkv, __half* __restrict__ out) {
    extern __shared__ char smc[];
    uint32_t smb = (uint32_t)__cvta_generic_to_shared(smc);
    const int b = blockIdx.z, h = blockIdx.y;
    const int q0 = blockIdx.x * 64;
    const int tid = threadIdx.x;
    const int lane = tid & 31;
    const int w = tid >> 5;
    const int gid = lane >> 2, tig = lane & 3;
    const int arow = lane & 15, alch = lane >> 4;
    const int b_nrow = (lane & 7) + ((lane >> 4) << 3);
    const int b_kc = (lane & 8) >> 3;
    const float scale = 0.125f;   // 1/sqrt(64)
    const uint32_t pbase = smb + 40960 + w * 2048;

    // ---- stage Q (pure copy) ----
    for (int i = tid; i < 512; i += 128) {
        int r = i >> 3, c = i & 7;
        const __half* src = qkv + ((size_t)(b * NN + q0 + r)) * C3 + h * DH + c * 8;
        CP_ASYNC16(smb + r * 128 + ((c ^ (r & 7)) << 4), src);
    }
    // ---- stage K/V tile 0 into buf 0 ----
    auto load_kv = [&](int buf, int kt) {
        uint32_t kb = smb + 8192 + buf * 8192;
        uint32_t vb = smb + 24576 + buf * 8192;
        for (int i = tid; i < 1024; i += 128) {
            int r = (i >> 3) & 63, c = i & 7;
            if (i < 512) {
                const __half* src = qkv + ((size_t)(b * NN + kt + r)) * C3 + CC + h * DH + c * 8;
                CP_ASYNC16(kb + r * 128 + ((c ^ (r & 7)) << 4), src);
            } else {
                const __half* src = qkv + ((size_t)(b * NN + kt + r)) * C3 + 2 * CC + h * DH + c * 8;
                CP_ASYNC16(vb + r * 128 + ((c ^ (r & 7)) << 4), src);
            }
        }
    };
    load_kv(0, 0);
    CP_COMMIT();

    float acco[8][4];
#pragma unroll
    for (int nt = 0; nt < 8; nt++)
#pragma unroll
        for (int j = 0; j < 4; j++) acco[nt][j] = 0.f;
    float m0 = -1e30f, m1 = -1e30f, l0 = 0.f, l1 = 0.f;

    const int NT = NN / 64;   // 32 tiles
    for (int it = 0; it < NT; it++) {
        int buf = it & 1;
        if (it + 1 < NT) {
            load_kv(buf ^ 1, (it + 1) * 64);
            CP_COMMIT();
            CP_WAIT(1);
        } else {
            CP_WAIT(0);
        }
        __syncthreads();

        uint32_t kb = smb + 8192 + buf * 8192;
        uint32_t vb = smb + 24576 + buf * 8192;

        // ---- S = Q K^T ----
        float accs[8][4];
#pragma unroll
        for (int nt = 0; nt < 8; nt++)
#pragma unroll
            for (int j = 0; j < 4; j++) accs[nt][j] = 0.f;

#pragma unroll
        for (int ks = 0; ks < 4; ks++) {
            uint32_t a0, a1, a2, a3;
            int qr = w * 16 + arow;
            uint32_t aaddr = smb + qr * 128 + (((ks * 2 + alch) ^ (arow & 7)) << 4);
            LDMATRIX_X4(a0, a1, a2, a3, aaddr);
#pragma unroll
            for (int p = 0; p < 4; p++) {
                int n = p * 16 + b_nrow;
                uint32_t baddr = kb + n * 128 + (((ks * 2 + b_kc) ^ (n & 7)) << 4);
                uint32_t f0, f1, f2, f3;
                LDMATRIX_X4(f0, f1, f2, f3, baddr);
                MMA_F16(accs[2*p][0], accs[2*p][1], accs[2*p][2], accs[2*p][3],
                        a0, a1, a2, a3, f0, f1);
                MMA_F16(accs[2*p+1][0], accs[2*p+1][1], accs[2*p+1][2], accs[2*p+1][3],
                        a0, a1, a2, a3, f2, f3);
            }
        }

        // ---- online softmax (scale folded here) ----
        float mx0 = -1e30f, mx1 = -1e30f;
#pragma unroll
        for (int nt = 0; nt < 8; nt++) {
            accs[nt][0] *= scale; accs[nt][1] *= scale;
            accs[nt][2] *= scale; accs[nt][3] *= scale;
            mx0 = fmaxf(mx0, fmaxf(accs[nt][0], accs[nt][1]));
            mx1 = fmaxf(mx1, fmaxf(accs[nt][2], accs[nt][3]));
        }
        mx0 = fmaxf(mx0, __shfl_xor_sync(0xffffffffu, mx0, 1));
        mx0 = fmaxf(mx0, __shfl_xor_sync(0xffffffffu, mx0, 2));
        mx1 = fmaxf(mx1, __shfl_xor_sync(0xffffffffu, mx1, 1));
        mx1 = fmaxf(mx1, __shfl_xor_sync(0xffffffffu, mx1, 2));
        float mn0 = fmaxf(m0, mx0), mn1 = fmaxf(m1, mx1);
        float cr0 = __expf(m0 - mn0), cr1 = __expf(m1 - mn1);
        float s0 = 0.f, s1 = 0.f;
#pragma unroll
        for (int nt = 0; nt < 8; nt++) {
            float p0 = __expf(accs[nt][0] - mn0);
            float p1 = __expf(accs[nt][1] - mn0);
            float p2 = __expf(accs[nt][2] - mn1);
            float p3 = __expf(accs[nt][3] - mn1);
            s0 += p0 + p1; s1 += p2 + p3;
            // store P as fp16 to per-warp smem
            __half2 lo = __floats2half2_rn(p0, p1);
            __half2 hi = __floats2half2_rn(p2, p3);
            uint32_t off0 = pbase + gid * 128 + ((nt ^ (gid & 7)) << 4) + tig * 4;
            uint32_t off1 = pbase + (gid + 8) * 128 + ((nt ^ ((gid + 8) & 7)) << 4) + tig * 4;
            asm volatile("st.shared.b32 [%0], %1;" :: "r"(off0), "r"(*(uint32_t*)&lo));
            asm volatile("st.shared.b32 [%0], %1;" :: "r"(off1), "r"(*(uint32_t*)&hi));
        }
        s0 += __shfl_xor_sync(0xffffffffu, s0, 1);
        s0 += __shfl_xor_sync(0xffffffffu, s0, 2);
        s1 += __shfl_xor_sync(0xffffffffu, s1, 1);
        s1 += __shfl_xor_sync(0xffffffffu, s1, 2);
        l0 = l0 * cr0 + s0; l1 = l1 * cr1 + s1;
        m0 = mn0; m1 = mn1;
#pragma unroll
        for (int nt = 0; nt < 8; nt++) {
            acco[nt][0] *= cr0; acco[nt][1] *= cr0;
            acco[nt][2] *= cr1; acco[nt][3] *= cr1;
        }
        __syncwarp();

        // ---- O += P V  (V natural layout; B-frags via ldmatrix.trans) ----
#pragma unroll
        for (int ks = 0; ks < 4; ks++) {
            uint32_t a0, a1, a2, a3;
            uint32_t aaddr = pbase + arow * 128 + (((ks * 2 + alch) ^ (arow & 7)) << 4);
            LDMATRIX_X4(a0, a1, a2, a3, aaddr);
#pragma unroll
            for (int p = 0; p < 4; p++) {
                int vr = ks * 16 + arow;               // key row
                int ch = p * 2 + alch;                 // d chunk
                uint32_t baddr = vb + vr * 128 + ((ch ^ (vr & 7)) << 4);
                uint32_t f0, f1, f2, f3;
                LDMATRIX_X4_T(f0, f1, f2, f3, baddr);
                MMA_F16(acco[2*p][0], acco[2*p][1], acco[2*p][2], acco[2*p][3],
                        a0, a1, a2, a3, f0, f1);
                MMA_F16(acco[2*p+1][0], acco[2*p+1][1], acco[2*p+1][2], acco[2*p+1][3],
                        a0, a1, a2, a3, f2, f3);
            }
        }
        __syncthreads();
    }

    // ---- epilogue ----
    float inv0 = 1.f / l0, inv1 = 1.f / l1;
#pragma unroll
    for (int nt = 0; nt < 8; nt++) {
        int col = h * DH + nt * 8 + tig * 2;
        size_t r0 = (size_t)(b * NN + q0 + w * 16 + gid) * CC + col;
        __half2 v0 = __floats2half2_rn(acco[nt][0] * inv0, acco[nt][1] * inv0);
        *(__half2*)&out[r0] = v0;
        size_t r1 = (size_t)(b * NN + q0 + w * 16 + gid + 8) * CC + col;
        __half2 v1 = __floats2half2_rn(acco[nt][2] * inv1, acco[nt][3] * inv1);
        *(__half2*)&out[r1] = v1;
    }
}

// ---------------- launch ----------------
extern "C" void kernel_launch(void* const* d_in, const int* in_sizes, int n_in,
                              void* d_out, int out_size) {
    const float* x      = (const float*)d_in[0];
    const float* pos    = (const float*)d_in[1];
    const float* Wqkv   = (const float*)d_in[2];
    const float* b_qkv  = (const float*)d_in[3];
    const float* lora_A = (const float*)d_in[4];
    const float* lora_B = (const float*)d_in[5];
    const float* Wproj  = (const float*)d_in[6];
    const float* b_proj = (const float*)d_in[7];
    const float* ln1_g  = (const float*)d_in[8];
    const float* ln1_b  = (const float*)d_in[9];
    const float* ln2_g  = (const float*)d_in[10];
    const float* ln2_b  = (const float*)d_in[11];
    const float* W1     = (const float*)d_in[12];
    const float* b1     = (const float*)d_in[13];
    const float* W2     = (const float*)d_in[14];
    const float* b2     = (const float*)d_in[15];
    float* out = (float*)d_out;

    float *p_x1, *p_x2, *p_afterA;
    __half *p_h, *p_qkv, *p_attn, *p_h2, *p_mlp;
    __half *p_wqkv, *p_wproj, *p_w1, *p_w2;
    cudaGetSymbolAddress((void**)&p_x1, g_x1);
    cudaGetSymbolAddress((void**)&p_x2, g_x2);
    cudaGetSymbolAddress((void**)&p_afterA, g_afterA);
    cudaGetSymbolAddress((void**)&p_h, g_h);
    cudaGetSymbolAddress((void**)&p_qkv, g_qkv);
    cudaGetSymbolAddress((void**)&p_attn, g_attn);
    cudaGetSymbolAddress((void**)&p_h2, g_h2);
    cudaGetSymbolAddress((void**)&p_mlp, g_mlp);
    cudaGetSymbolAddress((void**)&p_wqkv, g_wqkv_h);
    cudaGetSymbolAddress((void**)&p_wproj, g_wproj_h);
    cudaGetSymbolAddress((void**)&p_w1, g_w1_h);
    cudaGetSymbolAddress((void**)&p_w2, g_w2_h);

    static bool attr_set = false;
    if (!attr_set) {
        cudaFuncSetAttribute(gemm_f16_kernel,
                             cudaFuncAttributeMaxDynamicSharedMemorySize, 65536);
        cudaFuncSetAttribute(attn_f16_kernel,
                             cudaFuncAttributeMaxDynamicSharedMemorySize, 49152);
        attr_set = true;
    }

    // 0) weights -> fp16
    f2h_kernel<<<(C3 * CC / 8 + 255) / 256, 256>>>(Wqkv, p_wqkv, C3 * CC / 8);
    f2h_kernel<<<(CC * CC / 8 + 255) / 256, 256>>>(Wproj, p_wproj, CC * CC / 8);
    f2h_kernel<<<(MLPD * CC / 8 + 255) / 256, 256>>>(W1, p_w1, MLPD * CC / 8);
    f2h_kernel<<<(CC * MLPD / 8 + 255) / 256, 256>>>(W2, p_w2, CC * MLPD / 8);

    // 1) x1 = x + pos ; h = LN1(x1) (fp16)
    addpos_ln_kernel<<<MM, 256>>>(x, pos, ln1_g, ln1_b, p_x1, p_h);

    // 2) qkv = h @ Wqkv^T + b_qkv (fp16 out)
    gemm_f16_kernel<<<dim3(C3 / 128, MM / 128), 256, 65536>>>(
        p_h, p_wqkv, b_qkv, nullptr, nullptr, p_qkv, MM, C3, CC, 0);

    // 3) LoRA
    lora_afterA_kernel<<<MM, 256>>>(p_h, lora_A, p_afterA);
    lora_apply_kernel<<<(MM * CC) / 256, 256>>>(p_afterA, lora_B, p_qkv);

    // 4) attention (fp16 TC flash)
    attn_f16_kernel<<<dim3(NN / 64, HH, BB), 128, 49152>>>(p_qkv, p_attn);

    // 5) x2 = x1 + attn @ Wproj^T + b_proj (fp32 out)
    gemm_f16_kernel<<<dim3(CC / 128, MM / 128), 256, 65536>>>(
        p_attn, p_wproj, b_proj, p_x1, p_x2, nullptr, MM, CC, CC, 0);

    // 6) h2 = LN2(x2) (fp16)
    addpos_ln_kernel<<<MM, 256>>>(p_x2, nullptr, ln2_g, ln2_b, nullptr, p_h2);

    // 7) mlp = gelu(h2 @ W1^T + b1) (fp16 out)
    gemm_f16_kernel<<<dim3(MLPD / 128, MM / 128), 256, 65536>>>(
        p_h2, p_w1, b1, nullptr, nullptr, p_mlp, MM, MLPD, CC, 1);

    // 8) out = x2 + mlp @ W2^T + b2 (fp32 out)
    gemm_f16_kernel<<<dim3(CC / 128, MM / 128), 256, 65536>>>(
        p_mlp, p_w2, b2, p_x2, out, nullptr, MM, CC, MLPD, 0);
}